// round 13
// baseline (speedup 1.0000x reference)
#include <cuda_runtime.h>
#include <cuda_bf16.h>
#include <cstdint>

// out[m,n] = sum_k X[m,k]*W[n,k] + sum_r T[m,r]*A[n,r],  T = X @ B^T
// X:[256,8192] W:[8192,8192] A:[8192,16] B:[16,8192] f32. ALPHA=BETA=1.
// mma.sync.m16n8k8.tf32 (sm_103 PTX target: no tcgen05), raw f32 bits fed to
// tf32 mma (HW truncates; no cvt on ALU pipe).
// R10 = R9 (CTA 128x128, 8 warps 4Mx2N, warp tile 32x64) + fragment
// double-buffering: LDS batch for kk+1 issues before mma block for kk.

#define M_TOT 256
#define N_TOT 8192
#define K_TOT 8192
#define R_LORA 16

#define BM 128
#define BN 128
#define BK 32
#define NT (K_TOT / BK)       // 256
#define NSTG 4
#define XS_STRIDE 36          // 32 + 4 pad floats: conflict-free fragment LDS
#define X_STG (BM * XS_STRIDE)             // 4608 floats
#define W_STG (BN * XS_STRIDE)             // 4608 floats
#define STG_FLOATS (X_STG + W_STG)         // 9216
#define TS_STRIDE 17
#define AS_STRIDE 17
#define SMEM_FLOATS (NSTG * STG_FLOATS + BM * TS_STRIDE + BN * AS_STRIDE)
#define SMEM_BYTES (SMEM_FLOATS * 4)       // 164864

__device__ float g_T[M_TOT * R_LORA];

// ---------------------------------------------------------------------------
__device__ __forceinline__ void cp_async16(void* smem_dst, const void* gmem_src) {
    unsigned s = (unsigned)__cvta_generic_to_shared(smem_dst);
    asm volatile("cp.async.cg.shared.global [%0], [%1], 16;\n"
                 :: "r"(s), "l"(gmem_src) : "memory");
}
__device__ __forceinline__ void cp_commit() {
    asm volatile("cp.async.commit_group;\n" ::: "memory");
}
template <int N>
__device__ __forceinline__ void cp_wait() {
    asm volatile("cp.async.wait_group %0;\n" :: "n"(N) : "memory");
}
__device__ __forceinline__ void mma_tf32(float c[4], const unsigned a[4], const unsigned b[2]) {
    asm("mma.sync.aligned.m16n8k8.row.col.f32.tf32.tf32.f32 "
        "{%0,%1,%2,%3}, {%4,%5,%6,%7}, {%8,%9}, {%0,%1,%2,%3};\n"
        : "+f"(c[0]), "+f"(c[1]), "+f"(c[2]), "+f"(c[3])
        : "r"(a[0]), "r"(a[1]), "r"(a[2]), "r"(a[3]), "r"(b[0]), "r"(b[1]));
}

// ---------------------------------------------------------------------------
// Kernel 1: T[m,r] = sum_k X[m,k] * B[r,k]   (exact fp32, proven)
// ---------------------------------------------------------------------------
__global__ __launch_bounds__(256, 1) void lora_xbt_kernel(
    const float* __restrict__ X, const float* __restrict__ Bm)
{
    __shared__ float red[8][64];
    const int tid = threadIdx.x;
    const int m0 = blockIdx.x * 4;

    float acc[4][16];
#pragma unroll
    for (int mm = 0; mm < 4; mm++)
#pragma unroll
        for (int r = 0; r < 16; r++) acc[mm][r] = 0.f;

    for (int k0 = tid * 4; k0 < K_TOT; k0 += 256 * 4) {
        float4 xv[4];
#pragma unroll
        for (int mm = 0; mm < 4; mm++)
            xv[mm] = *reinterpret_cast<const float4*>(X + (size_t)(m0 + mm) * K_TOT + k0);
#pragma unroll
        for (int r = 0; r < 16; r++) {
            float4 bv = *reinterpret_cast<const float4*>(Bm + (size_t)r * K_TOT + k0);
#pragma unroll
            for (int mm = 0; mm < 4; mm++)
                acc[mm][r] += xv[mm].x * bv.x + xv[mm].y * bv.y +
                              xv[mm].z * bv.z + xv[mm].w * bv.w;
        }
    }
#pragma unroll
    for (int mm = 0; mm < 4; mm++)
#pragma unroll
        for (int r = 0; r < 16; r++) {
            float v = acc[mm][r];
#pragma unroll
            for (int o = 16; o > 0; o >>= 1) v += __shfl_xor_sync(0xffffffffu, v, o);
            if ((tid & 31) == 0) red[tid >> 5][mm * 16 + r] = v;
        }
    __syncthreads();
    if (tid < 64) {
        float s = 0.f;
#pragma unroll
        for (int w = 0; w < 8; w++) s += red[w][tid];
        g_T[(size_t)(m0 + (tid >> 4)) * 16 + (tid & 15)] = s;
    }
}

// ---------------------------------------------------------------------------
// Kernel 2: GEMM + LoRA epilogue.
// Grid 128 (1D): n-tile = bid & 63, m-half = bid >> 6.
// 256 threads = 8 warps in 4(M) x 2(N); warp tile 32x64 (mi=2, ni=8).
// 4-stage cp.async tile pipeline + 2-deep register fragment pipeline.
// ---------------------------------------------------------------------------
__global__ __launch_bounds__(256, 1) void lora_gemm_kernel(
    const float* __restrict__ X, const float* __restrict__ W,
    const float* __restrict__ A, float* __restrict__ Out)
{
    extern __shared__ float smem[];
    float* Ts = smem + NSTG * STG_FLOATS;              // 128 x 17
    float* As = Ts + BM * TS_STRIDE;                   // 128 x 17

    const int tid = threadIdx.x;
    const int n0 = (blockIdx.x & 63) * BN;
    const int m0g = (blockIdx.x >> 6) * BM;
    const int warp = tid >> 5;            // 0..7
    const int lane = tid & 31;
    const int g = lane >> 2;              // 0..7
    const int tig = lane & 3;             // 0..3
    const int mbase = (warp >> 1) * 32;   // 0,32,64,96  (4 M-slots)
    const int nbase = (warp & 1) * 64;    // 0,64        (2 N-slots)

    // stage LoRA operands (stride 17: conflict-free epilogue reads)
    for (int i = tid; i < BM * R_LORA; i += 256)
        Ts[(i >> 4) * TS_STRIDE + (i & 15)] = g_T[m0g * R_LORA + i];
    for (int i = tid; i < BN * R_LORA; i += 256)
        As[(i >> 4) * AS_STRIDE + (i & 15)] = A[(size_t)n0 * R_LORA + i];

    float c[2][8][4];
#pragma unroll
    for (int mi = 0; mi < 2; mi++)
#pragma unroll
        for (int ni = 0; ni < 8; ni++)
#pragma unroll
            for (int q = 0; q < 4; q++) c[mi][ni][q] = 0.f;

    // Loader: tile = 128 rows x 8 float4-granules = 1024 granules; thread
    // handles gid = tid + 256*j -> row = gid>>3 (0..127), col = (gid&7)*4.
#define LOAD_TILE(buf, kt)                                                     \
    do {                                                                       \
        float* xd_ = smem + (buf) * STG_FLOATS;                                \
        float* wd_ = xd_ + X_STG;                                              \
        _Pragma("unroll")                                                      \
        for (int j_ = 0; j_ < 4; j_++) {                                       \
            int gid_ = tid + 256 * j_;                                         \
            int row_ = gid_ >> 3;                                              \
            int col_ = (gid_ & 7) * 4;                                         \
            cp_async16(&xd_[row_ * XS_STRIDE + col_],                          \
                       X + (size_t)(m0g + row_) * K_TOT + (kt) + col_);        \
            cp_async16(&wd_[row_ * XS_STRIDE + col_],                          \
                       W + (size_t)(n0 + row_) * K_TOT + (kt) + col_);         \
        }                                                                      \
    } while (0)

    // Fragment load for k-step kk from tile buffers (xb_, wb_ in scope).
#define LOAD_FRAGS(kk, AF, BF)                                                 \
    do {                                                                       \
        const int k_ = (kk) * 8;                                               \
        _Pragma("unroll")                                                      \
        for (int mi_ = 0; mi_ < 2; mi_++) {                                    \
            const float* xr_ = xb_ + (mbase + mi_ * 16 + g) * XS_STRIDE + k_ + tig; \
            (AF)[mi_][0] = __float_as_uint(xr_[0]);                            \
            (AF)[mi_][1] = __float_as_uint(xr_[8 * XS_STRIDE]);                \
            (AF)[mi_][2] = __float_as_uint(xr_[4]);                            \
            (AF)[mi_][3] = __float_as_uint(xr_[8 * XS_STRIDE + 4]);            \
        }                                                                      \
        _Pragma("unroll")                                                      \
        for (int ni_ = 0; ni_ < 8; ni_++) {                                    \
            const float* wr_ = wb_ + (nbase + ni_ * 8 + g) * XS_STRIDE + k_ + tig; \
            (BF)[ni_][0] = __float_as_uint(wr_[0]);                            \
            (BF)[ni_][1] = __float_as_uint(wr_[4]);                            \
        }                                                                      \
    } while (0)

    // prologue: tiles 0,1,2 -> buffers 0,1,2
#pragma unroll
    for (int t = 0; t < NSTG - 1; t++) {
        LOAD_TILE(t, t * BK);
        cp_commit();
    }

    unsigned af[2][2][4], bf[2][8][2];   // 2-deep fragment pipeline

    for (int t = 0; t < NT; t++) {
        cp_wait<NSTG - 2>();   // tile t landed (this thread's groups)
        __syncthreads();       // everyone's tile t landed; compute t-1 done

        if (t + NSTG - 1 < NT)
            LOAD_TILE((t + NSTG - 1) & (NSTG - 1), (t + NSTG - 1) * BK);
        cp_commit();           // one group per iteration (possibly empty)

        const float* xb_ = smem + (t & (NSTG - 1)) * STG_FLOATS;
        const float* wb_ = xb_ + X_STG;

        LOAD_FRAGS(0, af[0], bf[0]);
#pragma unroll
        for (int kk = 0; kk < BK / 8; kk++) {
            const int cur = kk & 1, nxt = cur ^ 1;
            if (kk < BK / 8 - 1) LOAD_FRAGS(kk + 1, af[nxt], bf[nxt]);
#pragma unroll
            for (int mi = 0; mi < 2; mi++)
#pragma unroll
                for (int ni = 0; ni < 8; ni++)
                    mma_tf32(c[mi][ni], af[cur][mi], bf[cur][ni]);
        }
    }
    __syncthreads();

    // epilogue: exact fp32 rank-16 LoRA correction + direct stores
#pragma unroll
    for (int mi = 0; mi < 2; mi++) {
        const int m0r = mbase + mi * 16 + g;      // <= 119
        const int m1r = m0r + 8;                  // <= 127
#pragma unroll
        for (int ni = 0; ni < 8; ni++) {
            const int nl = nbase + ni * 8 + 2 * tig;   // <= 126
            float d00 = 0.f, d01 = 0.f, d10 = 0.f, d11 = 0.f;
#pragma unroll
            for (int r = 0; r < R_LORA; r++) {
                float t0 = Ts[m0r * TS_STRIDE + r];
                float t1 = Ts[m1r * TS_STRIDE + r];
                float a0 = As[nl * AS_STRIDE + r];
                float a1 = As[(nl + 1) * AS_STRIDE + r];
                d00 += t0 * a0;
                d01 += t0 * a1;
                d10 += t1 * a0;
                d11 += t1 * a1;
            }
            size_t o0 = (size_t)(m0g + m0r) * N_TOT + n0 + nl;   // row <= 255
            size_t o1 = (size_t)(m0g + m1r) * N_TOT + n0 + nl;
            float2 v0 = make_float2(c[mi][ni][0] + d00, c[mi][ni][1] + d01);
            float2 v1 = make_float2(c[mi][ni][2] + d10, c[mi][ni][3] + d11);
            *reinterpret_cast<float2*>(Out + o0) = v0;
            *reinterpret_cast<float2*>(Out + o1) = v1;
        }
    }
#undef LOAD_TILE
#undef LOAD_FRAGS
}

// ---------------------------------------------------------------------------
extern "C" void kernel_launch(void* const* d_in, const int* in_sizes, int n_in,
                              void* d_out, int out_size)
{
    const float* x  = (const float*)d_in[0];  // [4,64,8192]
    const float* W  = (const float*)d_in[1];  // [8192,8192]
    const float* A  = (const float*)d_in[2];  // [8192,16]
    const float* Bm = (const float*)d_in[3];  // [16,8192]
    float* out = (float*)d_out;               // [4,64,8192]

    cudaFuncSetAttribute(lora_gemm_kernel,
                         cudaFuncAttributeMaxDynamicSharedMemorySize, SMEM_BYTES);

    lora_xbt_kernel<<<64, 256>>>(x, Bm);
    lora_gemm_kernel<<<128, 256, SMEM_BYTES>>>(x, W, A, out);
}

// round 17
// speedup vs baseline: 1.0446x; 1.0446x over previous
#include <cuda_runtime.h>
#include <cuda_bf16.h>
#include <cstdint>

// out[m,n] = sum_k X[m,k]*W[n,k] + sum_r T[m,r]*A[n,r],  T = X @ B^T
// X:[256,8192] W:[8192,8192] A:[8192,16] B:[16,8192] f32. ALPHA=BETA=1.
// mma.sync.m16n8k8.tf32 (sm_103 PTX target: no tcgen05), raw f32 bits fed to
// tf32 mma (HW truncates; no cvt on ALU pipe).
// R14: CTA 128x128, 128 threads = 4 warps in 2(M) x 2(N), warp tile 64x64
//      (1.0 LDS/mma, 2x/2x fragment sharing -> smem crossbar 96KB/tile,
//      below the tensor floor). Fragment double-buffer is now load-bearing
//      (1 warp/SMSP).

#define M_TOT 256
#define N_TOT 8192
#define K_TOT 8192
#define R_LORA 16

#define BM 128
#define BN 128
#define BK 32
#define NT (K_TOT / BK)       // 256
#define NSTG 4
#define XS_STRIDE 36          // 32 + 4 pad floats: conflict-free fragment LDS
#define X_STG (BM * XS_STRIDE)             // 4608 floats
#define W_STG (BN * XS_STRIDE)             // 4608 floats
#define STG_FLOATS (X_STG + W_STG)         // 9216
#define TS_STRIDE 17
#define AS_STRIDE 17
#define SMEM_FLOATS (NSTG * STG_FLOATS + BM * TS_STRIDE + BN * AS_STRIDE)
#define SMEM_BYTES (SMEM_FLOATS * 4)       // 164864

__device__ float g_T[M_TOT * R_LORA];

// ---------------------------------------------------------------------------
__device__ __forceinline__ void cp_async16(void* smem_dst, const void* gmem_src) {
    unsigned s = (unsigned)__cvta_generic_to_shared(smem_dst);
    asm volatile("cp.async.cg.shared.global [%0], [%1], 16;\n"
                 :: "r"(s), "l"(gmem_src) : "memory");
}
__device__ __forceinline__ void cp_commit() {
    asm volatile("cp.async.commit_group;\n" ::: "memory");
}
template <int N>
__device__ __forceinline__ void cp_wait() {
    asm volatile("cp.async.wait_group %0;\n" :: "n"(N) : "memory");
}
__device__ __forceinline__ void mma_tf32(float c[4], const unsigned a[4], const unsigned b[2]) {
    asm("mma.sync.aligned.m16n8k8.row.col.f32.tf32.tf32.f32 "
        "{%0,%1,%2,%3}, {%4,%5,%6,%7}, {%8,%9}, {%0,%1,%2,%3};\n"
        : "+f"(c[0]), "+f"(c[1]), "+f"(c[2]), "+f"(c[3])
        : "r"(a[0]), "r"(a[1]), "r"(a[2]), "r"(a[3]), "r"(b[0]), "r"(b[1]));
}

// ---------------------------------------------------------------------------
// Kernel 1: T[m,r] = sum_k X[m,k] * B[r,k]   (exact fp32, proven)
// ---------------------------------------------------------------------------
__global__ __launch_bounds__(256, 1) void lora_xbt_kernel(
    const float* __restrict__ X, const float* __restrict__ Bm)
{
    __shared__ float red[8][64];
    const int tid = threadIdx.x;
    const int m0 = blockIdx.x * 4;

    float acc[4][16];
#pragma unroll
    for (int mm = 0; mm < 4; mm++)
#pragma unroll
        for (int r = 0; r < 16; r++) acc[mm][r] = 0.f;

    for (int k0 = tid * 4; k0 < K_TOT; k0 += 256 * 4) {
        float4 xv[4];
#pragma unroll
        for (int mm = 0; mm < 4; mm++)
            xv[mm] = *reinterpret_cast<const float4*>(X + (size_t)(m0 + mm) * K_TOT + k0);
#pragma unroll
        for (int r = 0; r < 16; r++) {
            float4 bv = *reinterpret_cast<const float4*>(Bm + (size_t)r * K_TOT + k0);
#pragma unroll
            for (int mm = 0; mm < 4; mm++)
                acc[mm][r] += xv[mm].x * bv.x + xv[mm].y * bv.y +
                              xv[mm].z * bv.z + xv[mm].w * bv.w;
        }
    }
#pragma unroll
    for (int mm = 0; mm < 4; mm++)
#pragma unroll
        for (int r = 0; r < 16; r++) {
            float v = acc[mm][r];
#pragma unroll
            for (int o = 16; o > 0; o >>= 1) v += __shfl_xor_sync(0xffffffffu, v, o);
            if ((tid & 31) == 0) red[tid >> 5][mm * 16 + r] = v;
        }
    __syncthreads();
    if (tid < 64) {
        float s = 0.f;
#pragma unroll
        for (int w = 0; w < 8; w++) s += red[w][tid];
        g_T[(size_t)(m0 + (tid >> 4)) * 16 + (tid & 15)] = s;
    }
}

// ---------------------------------------------------------------------------
// Kernel 2: GEMM + LoRA epilogue.
// Grid 128 (1D): n-tile = bid & 63, m-half = bid >> 6.
// 128 threads = 4 warps in 2(M) x 2(N); warp tile 64x64 (mi=4, ni=8).
// 4-stage cp.async tile pipeline + 2-deep register fragment pipeline.
// ---------------------------------------------------------------------------
__global__ __launch_bounds__(128, 1) void lora_gemm_kernel(
    const float* __restrict__ X, const float* __restrict__ W,
    const float* __restrict__ A, float* __restrict__ Out)
{
    extern __shared__ float smem[];
    float* Ts = smem + NSTG * STG_FLOATS;              // 128 x 17
    float* As = Ts + BM * TS_STRIDE;                   // 128 x 17

    const int tid = threadIdx.x;
    const int n0 = (blockIdx.x & 63) * BN;
    const int m0g = (blockIdx.x >> 6) * BM;
    const int warp = tid >> 5;            // 0..3
    const int lane = tid & 31;
    const int g = lane >> 2;              // 0..7
    const int tig = lane & 3;             // 0..3
    const int mbase = (warp >> 1) * 64;   // 0,64   (2 M-slots)
    const int nbase = (warp & 1) * 64;    // 0,64   (2 N-slots)

    // stage LoRA operands (stride 17: conflict-free epilogue reads)
    for (int i = tid; i < BM * R_LORA; i += 128)
        Ts[(i >> 4) * TS_STRIDE + (i & 15)] = g_T[m0g * R_LORA + i];
    for (int i = tid; i < BN * R_LORA; i += 128)
        As[(i >> 4) * AS_STRIDE + (i & 15)] = A[(size_t)n0 * R_LORA + i];

    float c[4][8][4];
#pragma unroll
    for (int mi = 0; mi < 4; mi++)
#pragma unroll
        for (int ni = 0; ni < 8; ni++)
#pragma unroll
            for (int q = 0; q < 4; q++) c[mi][ni][q] = 0.f;

    // Loader: X tile = 128 rows x 8 float4-granules = 1024 granules; 128
    // threads handle gid = tid + 128*j, j=0..7 -> row = gid>>3, col=(gid&7)*4.
#define LOAD_TILE(buf, kt)                                                     \
    do {                                                                       \
        float* xd_ = smem + (buf) * STG_FLOATS;                                \
        float* wd_ = xd_ + X_STG;                                              \
        _Pragma("unroll")                                                      \
        for (int j_ = 0; j_ < 8; j_++) {                                       \
            int gid_ = tid + 128 * j_;                                         \
            int row_ = gid_ >> 3;                                              \
            int col_ = (gid_ & 7) * 4;                                         \
            cp_async16(&xd_[row_ * XS_STRIDE + col_],                          \
                       X + (size_t)(m0g + row_) * K_TOT + (kt) + col_);        \
            cp_async16(&wd_[row_ * XS_STRIDE + col_],                          \
                       W + (size_t)(n0 + row_) * K_TOT + (kt) + col_);         \
        }                                                                      \
    } while (0)

    // Fragment load for k-step kk from tile buffers (xb_, wb_ in scope).
    // Rows: A = mbase+mi*16+g (+8) <= 64+48+7+8 = 127; B = nbase+ni*8+g <= 127.
#define LOAD_FRAGS(kk, AF, BF)                                                 \
    do {                                                                       \
        const int k_ = (kk) * 8;                                               \
        _Pragma("unroll")                                                      \
        for (int mi_ = 0; mi_ < 4; mi_++) {                                    \
            const float* xr_ = xb_ + (mbase + mi_ * 16 + g) * XS_STRIDE + k_ + tig; \
            (AF)[mi_][0] = __float_as_uint(xr_[0]);                            \
            (AF)[mi_][1] = __float_as_uint(xr_[8 * XS_STRIDE]);                \
            (AF)[mi_][2] = __float_as_uint(xr_[4]);                            \
            (AF)[mi_][3] = __float_as_uint(xr_[8 * XS_STRIDE + 4]);            \
        }                                                                      \
        _Pragma("unroll")                                                      \
        for (int ni_ = 0; ni_ < 8; ni_++) {                                    \
            const float* wr_ = wb_ + (nbase + ni_ * 8 + g) * XS_STRIDE + k_ + tig; \
            (BF)[ni_][0] = __float_as_uint(wr_[0]);                            \
            (BF)[ni_][1] = __float_as_uint(wr_[4]);                            \
        }                                                                      \
    } while (0)

    // prologue: tiles 0,1,2 -> buffers 0,1,2
#pragma unroll
    for (int t = 0; t < NSTG - 1; t++) {
        LOAD_TILE(t, t * BK);
        cp_commit();
    }

    unsigned af[2][4][4], bf[2][8][2];   // 2-deep fragment pipeline (64 regs)

    for (int t = 0; t < NT; t++) {
        cp_wait<NSTG - 2>();   // tile t landed (this thread's groups)
        __syncthreads();       // everyone's tile t landed; compute t-1 done

        if (t + NSTG - 1 < NT)
            LOAD_TILE((t + NSTG - 1) & (NSTG - 1), (t + NSTG - 1) * BK);
        cp_commit();           // one group per iteration (possibly empty)

        const float* xb_ = smem + (t & (NSTG - 1)) * STG_FLOATS;
        const float* wb_ = xb_ + X_STG;

        LOAD_FRAGS(0, af[0], bf[0]);
#pragma unroll
        for (int kk = 0; kk < BK / 8; kk++) {
            const int cur = kk & 1, nxt = cur ^ 1;
            if (kk < BK / 8 - 1) LOAD_FRAGS(kk + 1, af[nxt], bf[nxt]);
#pragma unroll
            for (int mi = 0; mi < 4; mi++)
#pragma unroll
                for (int ni = 0; ni < 8; ni++)
                    mma_tf32(c[mi][ni], af[cur][mi], bf[cur][ni]);
        }
    }
    __syncthreads();

    // epilogue: exact fp32 rank-16 LoRA correction + direct stores
#pragma unroll
    for (int mi = 0; mi < 4; mi++) {
        const int m0r = mbase + mi * 16 + g;      // <= 119
        const int m1r = m0r + 8;                  // <= 127
#pragma unroll
        for (int ni = 0; ni < 8; ni++) {
            const int nl = nbase + ni * 8 + 2 * tig;   // <= 126
            float d00 = 0.f, d01 = 0.f, d10 = 0.f, d11 = 0.f;
#pragma unroll
            for (int r = 0; r < R_LORA; r++) {
                float t0 = Ts[m0r * TS_STRIDE + r];
                float t1 = Ts[m1r * TS_STRIDE + r];
                float a0 = As[nl * AS_STRIDE + r];
                float a1 = As[(nl + 1) * AS_STRIDE + r];
                d00 += t0 * a0;
                d01 += t0 * a1;
                d10 += t1 * a0;
                d11 += t1 * a1;
            }
            size_t o0 = (size_t)(m0g + m0r) * N_TOT + n0 + nl;   // row <= 255
            size_t o1 = (size_t)(m0g + m1r) * N_TOT + n0 + nl;
            float2 v0 = make_float2(c[mi][ni][0] + d00, c[mi][ni][1] + d01);
            float2 v1 = make_float2(c[mi][ni][2] + d10, c[mi][ni][3] + d11);
            *reinterpret_cast<float2*>(Out + o0) = v0;
            *reinterpret_cast<float2*>(Out + o1) = v1;
        }
    }
#undef LOAD_TILE
#undef LOAD_FRAGS
}

// ---------------------------------------------------------------------------
extern "C" void kernel_launch(void* const* d_in, const int* in_sizes, int n_in,
                              void* d_out, int out_size)
{
    const float* x  = (const float*)d_in[0];  // [4,64,8192]
    const float* W  = (const float*)d_in[1];  // [8192,8192]
    const float* A  = (const float*)d_in[2];  // [8192,16]
    const float* Bm = (const float*)d_in[3];  // [16,8192]
    float* out = (float*)d_out;               // [4,64,8192]

    cudaFuncSetAttribute(lora_gemm_kernel,
                         cudaFuncAttributeMaxDynamicSharedMemorySize, SMEM_BYTES);

    lora_xbt_kernel<<<64, 256>>>(x, Bm);
    lora_gemm_kernel<<<128, 128, SMEM_BYTES>>>(x, W, A, out);
}